// round 13
// baseline (speedup 1.0000x reference)
#include <cuda_runtime.h>
#include <cuda_fp16.h>
#include <cstdint>

#define BATCH   128
#define NNODES  2047
#define DIN     512
#define NLAB    64

// ---------------------------------------------------------------------------
// Scratch (device globals)
// ---------------------------------------------------------------------------
__device__ __half  g_E[(size_t)BATCH * NNODES * NLAB];  // exp-form vectors u_g (fp16)
__device__ float   g_S[BATCH * NNODES];                 // per-node shift contributions
__device__ float2  g_expT[NLAB * 32];                   // f32 pairs for tail
__device__ __half  g_expTb[NLAB * NLAB];                // fp16 [k][l] = exp(trans[l][k])
__device__ __half  g_Wbf[DIN * NLAB];                   // W fp16 [k][n]
__device__ int     g_cnt[BATCH];                        // per-batch completion counters

// ---------------------------------------------------------------------------
// helpers
// ---------------------------------------------------------------------------
__device__ __forceinline__ uint32_t smem_u32(const void* p) {
    uint32_t a;
    asm("{ .reg .u64 t; cvta.to.shared.u64 t, %1; cvt.u32.u64 %0, t; }" : "=r"(a) : "l"(p));
    return a;
}
__device__ __forceinline__ void ldsm_x4(uint32_t* r, uint32_t addr) {
    asm volatile("ldmatrix.sync.aligned.m8n8.x4.shared.b16 {%0,%1,%2,%3}, [%4];"
                 : "=r"(r[0]), "=r"(r[1]), "=r"(r[2]), "=r"(r[3]) : "r"(addr));
}
__device__ __forceinline__ void ldsm_x4_t(uint32_t* r, uint32_t addr) {
    asm volatile("ldmatrix.sync.aligned.m8n8.x4.trans.shared.b16 {%0,%1,%2,%3}, [%4];"
                 : "=r"(r[0]), "=r"(r[1]), "=r"(r[2]), "=r"(r[3]) : "r"(addr));
}
__device__ __forceinline__ void mma_f16(float* c, const uint32_t* a, const uint32_t* b) {
    asm volatile(
        "mma.sync.aligned.m16n8k16.row.col.f32.f16.f16.f32 "
        "{%0,%1,%2,%3}, {%4,%5,%6,%7}, {%8,%9}, {%0,%1,%2,%3};"
        : "+f"(c[0]), "+f"(c[1]), "+f"(c[2]), "+f"(c[3])
        : "r"(a[0]), "r"(a[1]), "r"(a[2]), "r"(a[3]), "r"(b[0]), "r"(b[1]));
}
__device__ __forceinline__ void cp16(uint32_t sa, const void* g) {
    asm volatile("cp.async.cg.shared.global [%0], [%1], 16;" :: "r"(sa), "l"(g));
}
__device__ __forceinline__ uint32_t packh(float a, float b) {
    __half2 p = __floats2half2_rn(a, b);
    uint32_t u; memcpy(&u, &p, 4);
    return u;
}
__device__ __forceinline__ float2 h2f2(uint32_t u) {
    __half2 h; memcpy(&h, &u, 4);
    return __half22float2(h);
}

// ---------------------------------------------------------------------------
// Fused init: g_Wbf, g_expT, g_expTb, g_cnt — one launch (R9 scheme)
// ---------------------------------------------------------------------------
__global__ void init_all(const float* __restrict__ trans, const float* __restrict__ W) {
    int idx = blockIdx.x * blockDim.x + threadIdx.x;
    if (idx < DIN * NLAB) g_Wbf[idx] = __float2half(W[idx]);
    if (idx < NLAB * 32) {
        int k = idx >> 5, j = idx & 31;
        g_expT[idx] = make_float2(expf(trans[j * NLAB + k]),
                                  expf(trans[(j + 32) * NLAB + k]));
    }
    if (idx < NLAB * NLAB) {
        int k = idx >> 6, l = idx & 63;
        g_expTb[idx] = __float2half(expf(trans[l * NLAB + k]));
    }
    if (idx < BATCH) g_cnt[idx] = 0;
}

// ---------------------------------------------------------------------------
// GEMM: 4-stage cp.async pipeline (prefetch depth 3), f32 A at stride 40
// (conflict-free LDS.64 fragment reads) + fp16 W.  Race-free commit
// discipline: one commit_group EVERY iteration so wait_group 2 provably
// completes chunk c; wait_group 0 before the epilogue's Af overlay.
// ---------------------------------------------------------------------------
#define AF_STR 40
#define AF_SZ  (128 * AF_STR)
#define WS_STR 72
#define WS_SZ  (32 * WS_STR)
#define NCH    16

__global__ __launch_bounds__(256)
void gemm_kernel(const float* __restrict__ A, const float* __restrict__ bias) {
    __shared__ float  Af[4][AF_SZ];      // 81920 B
    __shared__ __half Ws[4][WS_SZ];      // 18432 B
    __shared__ float bs[NLAB];

    const int tid = threadIdx.x;
    if (tid < NLAB) bs[tid] = bias[tid];

    const int wm = tid >> 5, lane = tid & 31;
    const int grp = lane >> 2, tig = lane & 3;
    const size_t r0 = (size_t)blockIdx.x * 128;

    const uint32_t af_b = smem_u32(&Af[0][0]);
    const uint32_t ws_b = smem_u32(&Ws[0][0]);
    const char* Abase = (const char*)(A + r0 * DIN);
    const char* Wbase = (const char*)g_Wbf;

    const int a_row = tid >> 3, a_c4 = tid & 7;
    const int w_row = tid >> 3, w_c8 = tid & 7;

#define ISSUE(c, st)                                                            \
    do {                                                                        \
        const char* Ag = Abase + (size_t)(c) * 128;                             \
        _Pragma("unroll")                                                       \
        for (int p = 0; p < 4; p++) {                                           \
            int row = a_row + p * 32;                                           \
            cp16(af_b + (uint32_t)((st) * AF_SZ + row * AF_STR + a_c4 * 4) * 4, \
                 Ag + (size_t)row * 2048 + a_c4 * 16);                          \
        }                                                                       \
        cp16(ws_b + (uint32_t)((st) * WS_SZ + w_row * WS_STR + w_c8 * 8) * 2,   \
             Wbase + ((c) * 32 + w_row) * 128 + w_c8 * 16);                     \
    } while (0)
#define COMMIT() asm volatile("cp.async.commit_group;")

    float acc[8][4] = {};

    ISSUE(0, 0); COMMIT();
    ISSUE(1, 1); COMMIT();
    ISSUE(2, 2); COMMIT();

#pragma unroll 1
    for (int c = 0; c < NCH; c++) {
        asm volatile("cp.async.wait_group 2;");
        __syncthreads();
        if (c + 3 < NCH) ISSUE(c + 3, (c + 3) & 3);
        COMMIT();   // unconditional: group count stays c+3 -> wait_group 2 == chunk c done

        const int st = c & 3;
        const float* af = Af[st];
        const uint32_t wsb = ws_b + (uint32_t)(st * WS_SZ) * 2;

#pragma unroll
        for (int kk = 0; kk < 2; kk++) {
            const int k0 = kk * 16 + tig * 2;
            uint32_t a[4], bbv[4][4];
            {
                float2 p00 = *(const float2*)&af[(wm * 16 + grp)     * AF_STR + k0];
                float2 p10 = *(const float2*)&af[(wm * 16 + grp + 8) * AF_STR + k0];
                float2 p01 = *(const float2*)&af[(wm * 16 + grp)     * AF_STR + k0 + 8];
                float2 p11 = *(const float2*)&af[(wm * 16 + grp + 8) * AF_STR + k0 + 8];
                a[0] = packh(p00.x, p00.y);
                a[1] = packh(p10.x, p10.y);
                a[2] = packh(p01.x, p01.y);
                a[3] = packh(p11.x, p11.y);
            }
#pragma unroll
            for (int nt = 0; nt < 4; nt++)
                ldsm_x4_t(bbv[nt], wsb + (uint32_t)((kk * 16 + (lane & 15)) * WS_STR
                                                    + nt * 16 + ((lane >> 4) << 3)) * 2);
#pragma unroll
            for (int nt = 0; nt < 4; nt++) {
                mma_f16(acc[nt * 2],     a, &bbv[nt][0]);
                mma_f16(acc[nt * 2 + 1], a, &bbv[nt][2]);
            }
        }
    }
#undef ISSUE
#undef COMMIT

    // ALL groups must land before Af is reused as epilogue staging
    asm volatile("cp.async.wait_group 0;");
    __syncthreads();

    // Epilogue: +bias, row max, exp, fp16 store + g_S
    const int r0l = wm * 16 + grp;
    float v0[16], v1[16];
    float m0 = -1e30f, m1 = -1e30f;
#pragma unroll
    for (int nb = 0; nb < 8; nb++) {
#pragma unroll
        for (int h = 0; h < 2; h++) {
            int cc = nb * 8 + tig * 2 + h;
            float x0 = acc[nb][h]     + bs[cc];
            float x1 = acc[nb][2 + h] + bs[cc];
            v0[nb * 2 + h] = x0; v1[nb * 2 + h] = x1;
            m0 = fmaxf(m0, x0); m1 = fmaxf(m1, x1);
        }
    }
    m0 = fmaxf(m0, __shfl_xor_sync(0xffffffffu, m0, 1));
    m0 = fmaxf(m0, __shfl_xor_sync(0xffffffffu, m0, 2));
    m1 = fmaxf(m1, __shfl_xor_sync(0xffffffffu, m1, 1));
    m1 = fmaxf(m1, __shfl_xor_sync(0xffffffffu, m1, 2));

    __half* stage = (__half*)Af;   // 128 x 72 fp16 staging (safe after wait_group 0)
#pragma unroll
    for (int nb = 0; nb < 8; nb++) {
        *(uint32_t*)&stage[r0l * 72 + nb * 8 + tig * 2] =
            packh(__expf(v0[nb * 2] - m0), __expf(v0[nb * 2 + 1] - m0));
        *(uint32_t*)&stage[(r0l + 8) * 72 + nb * 8 + tig * 2] =
            packh(__expf(v1[nb * 2] - m1), __expf(v1[nb * 2 + 1] - m1));
    }
    if (tig == 0) { g_S[r0 + r0l] = m0; g_S[r0 + r0l + 8] = m1; }
    __syncwarp();
#pragma unroll
    for (int p = 0; p < 4; p++) {
        int q = lane + 32 * p;
        int rr = q >> 3, c16 = q & 7;
        uint4 d = *(uint4*)&stage[(wm * 16 + rr) * 72 + c16 * 8];
        *(uint4*)&g_E[(r0 + wm * 16 + rr) * 64 + c16 * 8] = d;
    }
}

// ---------------------------------------------------------------------------
// Subtree kernel + fused tail.  expTb loaded COALESCED via cp.async from the
// precomputed global (R9 scheme); Par double-buffered (prefetch under MMA).
// ---------------------------------------------------------------------------
__global__ __launch_bounds__(256)
void subtree_kernel(float* __restrict__ out) {
    __shared__ __align__(16) char blob[45056];
    __shared__ float warpS[8];
    __shared__ float nodeLog[8];
    __shared__ float sGlob;
    __shared__ int   is_last;

    __half* Cur = (__half*)blob;              // 128*72*2 = 18432
    __half* Tb  = (__half*)(blob + 18432);    //  64*72*2 =  9216
    __half* Par = (__half*)(blob + 27648);    // 2 x 64*64*2 = 16384

    const int tid = threadIdx.x;
    const int wm = tid >> 5, lane = tid & 31;
    const int grp = lane >> 2, tig = lane & 3;
    const int b = blockIdx.x >> 3, j = blockIdx.x & 7;
    const size_t nb_base = (size_t)b * NNODES;

    const uint32_t cur_b = smem_u32(Cur), tb_b = smem_u32(Tb);
    const uint32_t par_b = smem_u32(Par);

    // initial loads: 128 leaf rows, expTb (coalesced), Par[0] for P=64
    const char* Lg = (const char*)(g_E + (nb_base + 1023 + 128 * j) * 64);
    for (int q = tid; q < 1024; q += 256) {
        int r = q >> 3, c = q & 7;
        cp16(cur_b + (uint32_t)(r * 72 + c * 8) * 2, Lg + q * 16);
    }
    const char* Tg = (const char*)g_expTb;
    for (int q = tid; q < 512; q += 256) {
        int r = q >> 3, c = q & 7;
        cp16(tb_b + (uint32_t)(r * 72 + c * 8) * 2, Tg + q * 16);
    }
    {
        const char* Pg = (const char*)(g_E + (nb_base + 511 + 64 * j) * 64);
        for (int q = tid; q < 512; q += 256)
            cp16(par_b + (uint32_t)(q * 16), Pg + q * 16);
    }
    asm volatile("cp.async.commit_group;");
    asm volatile("cp.async.wait_group 0;");
    __syncthreads();

    float lsum = 0.f;
    int parsel = 0;

#pragma unroll 1
    for (int P = 64; P >= 1; P >>= 1) {
        const int active = (wm * 16) < 2 * P;

        // prefetch NEXT level's parent rows into the other Par buffer
        if (P > 1) {
            const char* Pg = (const char*)(g_E + (nb_base + 4 * P - 1 + (P / 2) * j) * 64);
            const uint32_t pb = par_b + (uint32_t)(parsel ^ 1) * 8192;
            for (int q = tid; q < 4 * P; q += 256)
                cp16(pb + (uint32_t)(q * 16), Pg + q * 16);
            asm volatile("cp.async.commit_group;");
        }

        float acc[8][4];
#pragma unroll
        for (int nb = 0; nb < 8; nb++)
#pragma unroll
            for (int i = 0; i < 4; i++) acc[nb][i] = 0.f;

        if (active) {
#pragma unroll
            for (int kk = 0; kk < 4; kk++) {
                uint32_t a[4], bbv[4][4];
                ldsm_x4(a, cur_b + (uint32_t)((wm * 16 + (lane & 15)) * 72
                                              + kk * 16 + ((lane >> 4) << 3)) * 2);
#pragma unroll
                for (int nt = 0; nt < 4; nt++)
                    ldsm_x4_t(bbv[nt], tb_b + (uint32_t)((kk * 16 + (lane & 15)) * 72
                                                         + nt * 16 + ((lane >> 4) << 3)) * 2);
#pragma unroll
                for (int nt = 0; nt < 4; nt++) {
                    mma_f16(acc[nt * 2],     a, &bbv[nt][0]);
                    mma_f16(acc[nt * 2 + 1], a, &bbv[nt][2]);
                }
            }
        }
        __syncthreads();   // all Cur reads done -> epilogue may write Cur

        if (active) {
            const int p0 = wm * 8 + (grp >> 1);
            const int p1 = p0 + 4;
            const bool ok0 = p0 < P, ok1 = p1 < P;
            const __half* par = Par + parsel * 4096;

            float q0[16], q1[16];
            float C0 = 0.f, C1 = 0.f;
#pragma unroll
            for (int nb = 0; nb < 8; nb++) {
                float s00 = acc[nb][0], s01 = acc[nb][1];
                float s10 = acc[nb][2], s11 = acc[nb][3];
                float p00 = s00 * __shfl_xor_sync(0xffffffffu, s00, 4);
                float p01 = s01 * __shfl_xor_sync(0xffffffffu, s01, 4);
                float p10 = s10 * __shfl_xor_sync(0xffffffffu, s10, 4);
                float p11 = s11 * __shfl_xor_sync(0xffffffffu, s11, 4);
                uint32_t e0u = ok0 ? *(const uint32_t*)&par[p0 * 64 + nb * 8 + tig * 2] : 0u;
                uint32_t e1u = ok1 ? *(const uint32_t*)&par[p1 * 64 + nb * 8 + tig * 2] : 0u;
                float2 e0 = h2f2(e0u), e1 = h2f2(e1u);
                q0[nb * 2]     = e0.x * p00;
                q0[nb * 2 + 1] = e0.y * p01;
                q1[nb * 2]     = e1.x * p10;
                q1[nb * 2 + 1] = e1.y * p11;
                C0 = fmaxf(C0, fmaxf(q0[nb * 2], q0[nb * 2 + 1]));
                C1 = fmaxf(C1, fmaxf(q1[nb * 2], q1[nb * 2 + 1]));
            }
            C0 = fmaxf(C0, __shfl_xor_sync(0xffffffffu, C0, 1));
            C0 = fmaxf(C0, __shfl_xor_sync(0xffffffffu, C0, 2));
            C1 = fmaxf(C1, __shfl_xor_sync(0xffffffffu, C1, 1));
            C1 = fmaxf(C1, __shfl_xor_sync(0xffffffffu, C1, 2));
            float i0 = __fdividef(1.0f, C0), i1 = __fdividef(1.0f, C1);

            if (!(grp & 1)) {
                if (ok0) {
#pragma unroll
                    for (int nb = 0; nb < 8; nb++)
                        *(uint32_t*)&Cur[p0 * 72 + nb * 8 + tig * 2] =
                            packh(q0[nb * 2] * i0, q0[nb * 2 + 1] * i0);
                }
                if (ok1) {
#pragma unroll
                    for (int nb = 0; nb < 8; nb++)
                        *(uint32_t*)&Cur[p1 * 72 + nb * 8 + tig * 2] =
                            packh(q1[nb * 2] * i1, q1[nb * 2 + 1] * i1);
                }
                if (tig == 0) {
                    if (ok0) lsum += __logf(C0);
                    if (ok1) lsum += __logf(C1);
                }
            }
        }
        asm volatile("cp.async.wait_group 0;");  // next Par arrived (overlapped)
        __syncthreads();
        parsel ^= 1;
    }

    if (tid < 8)
        *(uint4*)&g_E[(nb_base + 7 + j) * 64 + tid * 8] = *(uint4*)&Cur[tid * 8];

#pragma unroll
    for (int o = 16; o > 0; o >>= 1) lsum += __shfl_xor_sync(0xffffffffu, lsum, o);
    if (lane == 0) warpS[wm] = lsum;
    __syncthreads();
    if (tid == 0) {
        float t = 0.f;
        for (int i = 0; i < 8; i++) t += warpS[i];
        g_S[nb_base + 7 + j] += t;
    }

    // -------- completion protocol: last CTA of this batch runs the tail -----
    __threadfence();
    __syncthreads();
    if (tid == 0) {
        int old = atomicAdd(&g_cnt[b], 1);
        is_last = (old == 7);
    }
    __syncthreads();
    if (!is_last) return;
    __threadfence();

    // -------- tail phase (overlaid smem) ------------------------------------
    float*  Eb  = (float*)blob;            // 15*64*4 = 3840
    float2* Ept = (float2*)(blob + 4096);  // 2048*8 = 16384

    for (int i = tid; i < NLAB * 32; i += 256) Ept[i] = g_expT[i];
    const uint32_t* srcE = (const uint32_t*)(g_E + nb_base * 64);
    for (int i = tid; i < 480; i += 256) {
        float2 f = h2f2(srcE[i]);
        Eb[2 * i]     = f.x;
        Eb[2 * i + 1] = f.y;
    }
    float s = 0.f;
    const float* Sb = g_S + nb_base;
    for (int i = tid; i < NNODES; i += 256) s += Sb[i];
#pragma unroll
    for (int o = 16; o > 0; o >>= 1) s += __shfl_xor_sync(0xffffffffu, s, o);
    if (lane == 0) warpS[wm] = s;
    __syncthreads();
    if (tid == 0) {
        float t = 0.f;
        for (int i = 0; i < 8; i++) t += warpS[i];
        sGlob = t;
    }
    __syncthreads();

    // phase 1: nodes 3..6 on warps 0..3
    if (wm < 4) {
        int p = 3 + wm, cL = 2 * p + 1, cR = 2 * p + 2;
        float aL0 = 0.f, aL1 = 0.f, aR0 = 0.f, aR1 = 0.f;
#pragma unroll
        for (int k = 0; k < NLAB; k++) {
            float2 tt = Ept[k * 32 + lane];
            float uL = Eb[cL * 64 + k], uR = Eb[cR * 64 + k];
            aL0 = fmaf(tt.x, uL, aL0); aL1 = fmaf(tt.y, uL, aL1);
            aR0 = fmaf(tt.x, uR, aR0); aR1 = fmaf(tt.y, uR, aR1);
        }
        float q0 = Eb[p * 64 + lane]      * aL0 * aR0;
        float q1 = Eb[p * 64 + lane + 32] * aL1 * aR1;
        float C = fmaxf(q0, q1);
#pragma unroll
        for (int o = 16; o > 0; o >>= 1) C = fmaxf(C, __shfl_xor_sync(0xffffffffu, C, o));
        float inv = __fdividef(1.0f, C);
        Eb[p * 64 + lane]      = q0 * inv;
        Eb[p * 64 + lane + 32] = q1 * inv;
        if (lane == 0) nodeLog[wm] = __logf(C);
    }
    __syncthreads();

    // phase 2: nodes 1,2 on warps 0,1
    if (wm < 2) {
        int p = 1 + wm, cL = 2 * p + 1, cR = 2 * p + 2;
        float aL0 = 0.f, aL1 = 0.f, aR0 = 0.f, aR1 = 0.f;
#pragma unroll
        for (int k = 0; k < NLAB; k++) {
            float2 tt = Ept[k * 32 + lane];
            float uL = Eb[cL * 64 + k], uR = Eb[cR * 64 + k];
            aL0 = fmaf(tt.x, uL, aL0); aL1 = fmaf(tt.y, uL, aL1);
            aR0 = fmaf(tt.x, uR, aR0); aR1 = fmaf(tt.y, uR, aR1);
        }
        float q0 = Eb[p * 64 + lane]      * aL0 * aR0;
        float q1 = Eb[p * 64 + lane + 32] * aL1 * aR1;
        float C = fmaxf(q0, q1);
#pragma unroll
        for (int o = 16; o > 0; o >>= 1) C = fmaxf(C, __shfl_xor_sync(0xffffffffu, C, o));
        float inv = __fdividef(1.0f, C);
        Eb[p * 64 + lane]      = q0 * inv;
        Eb[p * 64 + lane + 32] = q1 * inv;
        if (lane == 0) nodeLog[4 + wm] = __logf(C);
    }
    __syncthreads();

    // phase 3: root on warp 0
    if (wm == 0) {
        float aL0 = 0.f, aL1 = 0.f, aR0 = 0.f, aR1 = 0.f;
#pragma unroll
        for (int k = 0; k < NLAB; k++) {
            float2 tt = Ept[k * 32 + lane];
            float uL = Eb[64 + k], uR = Eb[128 + k];
            aL0 = fmaf(tt.x, uL, aL0); aL1 = fmaf(tt.y, uL, aL1);
            aR0 = fmaf(tt.x, uR, aR0); aR1 = fmaf(tt.y, uR, aR1);
        }
        float q0 = Eb[lane]      * aL0 * aR0;
        float q1 = Eb[lane + 32] * aL1 * aR1;
        float S = sGlob + nodeLog[0] + nodeLog[1] + nodeLog[2]
                        + nodeLog[3] + nodeLog[4] + nodeLog[5];
        out[b * NLAB + lane]      = S + __logf(q0);
        out[b * NLAB + lane + 32] = S + __logf(q1);
    }
}

// ---------------------------------------------------------------------------
// Launcher
// ---------------------------------------------------------------------------
extern "C" void kernel_launch(void* const* d_in, const int* in_sizes, int n_in,
                              void* d_out, int out_size) {
    const float* hidden = (const float*)d_in[0];
    const float* W      = (const float*)d_in[1];
    const float* bias   = (const float*)d_in[2];
    const float* trans  = (const float*)d_in[3];
    float* out = (float*)d_out;

    init_all<<<128, 256>>>(trans, W);
    gemm_kernel<<<NNODES, 256>>>(hidden, bias);
    subtree_kernel<<<BATCH * 8, 256>>>(out);
}

// round 14
// speedup vs baseline: 1.4758x; 1.4758x over previous
#include <cuda_runtime.h>
#include <cuda_fp16.h>
#include <cstdint>

#define BATCH   128
#define NNODES  2047
#define DIN     512
#define NLAB    64

// ---------------------------------------------------------------------------
// Scratch (device globals)
// ---------------------------------------------------------------------------
__device__ __half  g_E[(size_t)BATCH * NNODES * NLAB];  // exp-form vectors u_g (fp16)
__device__ float   g_S[BATCH * NNODES];                 // per-node shift contributions
__device__ float2  g_expT[NLAB * 32];                   // f32 pairs for tail
__device__ __half  g_expTb[NLAB * NLAB];                // fp16 [k][l] = exp(trans[l][k])
__device__ __half  g_Wbf[DIN * NLAB];                   // W fp16 [k][n]
__device__ int     g_cnt[BATCH];                        // per-batch completion counters

// ---------------------------------------------------------------------------
// helpers
// ---------------------------------------------------------------------------
__device__ __forceinline__ uint32_t smem_u32(const void* p) {
    uint32_t a;
    asm("{ .reg .u64 t; cvta.to.shared.u64 t, %1; cvt.u32.u64 %0, t; }" : "=r"(a) : "l"(p));
    return a;
}
__device__ __forceinline__ void ldsm_x4(uint32_t* r, uint32_t addr) {
    asm volatile("ldmatrix.sync.aligned.m8n8.x4.shared.b16 {%0,%1,%2,%3}, [%4];"
                 : "=r"(r[0]), "=r"(r[1]), "=r"(r[2]), "=r"(r[3]) : "r"(addr));
}
__device__ __forceinline__ void ldsm_x4_t(uint32_t* r, uint32_t addr) {
    asm volatile("ldmatrix.sync.aligned.m8n8.x4.trans.shared.b16 {%0,%1,%2,%3}, [%4];"
                 : "=r"(r[0]), "=r"(r[1]), "=r"(r[2]), "=r"(r[3]) : "r"(addr));
}
__device__ __forceinline__ void mma_f16(float* c, const uint32_t* a, const uint32_t* b) {
    asm volatile(
        "mma.sync.aligned.m16n8k16.row.col.f32.f16.f16.f32 "
        "{%0,%1,%2,%3}, {%4,%5,%6,%7}, {%8,%9}, {%0,%1,%2,%3};"
        : "+f"(c[0]), "+f"(c[1]), "+f"(c[2]), "+f"(c[3])
        : "r"(a[0]), "r"(a[1]), "r"(a[2]), "r"(a[3]), "r"(b[0]), "r"(b[1]));
}
__device__ __forceinline__ void cp16(uint32_t sa, const void* g) {
    asm volatile("cp.async.cg.shared.global [%0], [%1], 16;" :: "r"(sa), "l"(g));
}
__device__ __forceinline__ uint32_t packh(float a, float b) {
    __half2 p = __floats2half2_rn(a, b);
    uint32_t u; memcpy(&u, &p, 4);
    return u;
}
__device__ __forceinline__ float2 h2f2(uint32_t u) {
    __half2 h; memcpy(&h, &u, 4);
    return __half22float2(h);
}

// ---------------------------------------------------------------------------
// Fused init (vectorized W path): g_Wbf, g_expT, g_expTb, g_cnt — one launch
// grid 32 x 256 = 8192 threads; W handled as 8192 float4.
// ---------------------------------------------------------------------------
__global__ void init_all(const float* __restrict__ trans, const float* __restrict__ W) {
    int idx = blockIdx.x * blockDim.x + threadIdx.x;
    {
        float4 w = ((const float4*)W)[idx];
        uint2 p;
        p.x = packh(w.x, w.y);
        p.y = packh(w.z, w.w);
        *(uint2*)&g_Wbf[idx * 4] = p;
    }
    if (idx < NLAB * 32) {
        int k = idx >> 5, j = idx & 31;
        g_expT[idx] = make_float2(expf(trans[j * NLAB + k]),
                                  expf(trans[(j + 32) * NLAB + k]));
    }
    if (idx < NLAB * NLAB) {
        int k = idx >> 6, l = idx & 63;
        g_expTb[idx] = __float2half(expf(trans[l * NLAB + k]));
    }
    if (idx < BATCH) g_cnt[idx] = 0;
}

// ---------------------------------------------------------------------------
// GEMM: 4-stage cp.async pipeline (prefetch depth 3), f32 A at stride 40
// (conflict-free LDS.64 fragment reads) + fp16 W.  Race-free commit
// discipline: one commit_group EVERY iteration so wait_group 2 provably
// completes chunk c; wait_group 0 before the epilogue's Af overlay.
// ---------------------------------------------------------------------------
#define AF_STR 40
#define AF_SZ  (128 * AF_STR)
#define WS_STR 72
#define WS_SZ  (32 * WS_STR)
#define NCH    16

__global__ __launch_bounds__(256)
void gemm_kernel(const float* __restrict__ A, const float* __restrict__ bias) {
    __shared__ float  Af[4][AF_SZ];      // 81920 B
    __shared__ __half Ws[4][WS_SZ];      // 18432 B
    __shared__ float bs[NLAB];

    const int tid = threadIdx.x;
    if (tid < NLAB) bs[tid] = bias[tid];

    const int wm = tid >> 5, lane = tid & 31;
    const int grp = lane >> 2, tig = lane & 3;
    const size_t r0 = (size_t)blockIdx.x * 128;

    const uint32_t af_b = smem_u32(&Af[0][0]);
    const uint32_t ws_b = smem_u32(&Ws[0][0]);
    const char* Abase = (const char*)(A + r0 * DIN);
    const char* Wbase = (const char*)g_Wbf;

    const int a_row = tid >> 3, a_c4 = tid & 7;
    const int w_row = tid >> 3, w_c8 = tid & 7;

#define ISSUE(c, st)                                                            \
    do {                                                                        \
        const char* Ag = Abase + (size_t)(c) * 128;                             \
        _Pragma("unroll")                                                       \
        for (int p = 0; p < 4; p++) {                                           \
            int row = a_row + p * 32;                                           \
            cp16(af_b + (uint32_t)((st) * AF_SZ + row * AF_STR + a_c4 * 4) * 4, \
                 Ag + (size_t)row * 2048 + a_c4 * 16);                          \
        }                                                                       \
        cp16(ws_b + (uint32_t)((st) * WS_SZ + w_row * WS_STR + w_c8 * 8) * 2,   \
             Wbase + ((c) * 32 + w_row) * 128 + w_c8 * 16);                     \
    } while (0)
#define COMMIT() asm volatile("cp.async.commit_group;")

    float acc[8][4] = {};

    ISSUE(0, 0); COMMIT();
    ISSUE(1, 1); COMMIT();
    ISSUE(2, 2); COMMIT();

#pragma unroll 1
    for (int c = 0; c < NCH; c++) {
        asm volatile("cp.async.wait_group 2;");
        __syncthreads();
        if (c + 3 < NCH) ISSUE(c + 3, (c + 3) & 3);
        COMMIT();   // unconditional: group count stays c+3 -> wait_group 2 == chunk c done

        const int st = c & 3;
        const float* af = Af[st];
        const uint32_t wsb = ws_b + (uint32_t)(st * WS_SZ) * 2;

#pragma unroll
        for (int kk = 0; kk < 2; kk++) {
            const int k0 = kk * 16 + tig * 2;
            uint32_t a[4], bbv[4][4];
            {
                float2 p00 = *(const float2*)&af[(wm * 16 + grp)     * AF_STR + k0];
                float2 p10 = *(const float2*)&af[(wm * 16 + grp + 8) * AF_STR + k0];
                float2 p01 = *(const float2*)&af[(wm * 16 + grp)     * AF_STR + k0 + 8];
                float2 p11 = *(const float2*)&af[(wm * 16 + grp + 8) * AF_STR + k0 + 8];
                a[0] = packh(p00.x, p00.y);
                a[1] = packh(p10.x, p10.y);
                a[2] = packh(p01.x, p01.y);
                a[3] = packh(p11.x, p11.y);
            }
#pragma unroll
            for (int nt = 0; nt < 4; nt++)
                ldsm_x4_t(bbv[nt], wsb + (uint32_t)((kk * 16 + (lane & 15)) * WS_STR
                                                    + nt * 16 + ((lane >> 4) << 3)) * 2);
#pragma unroll
            for (int nt = 0; nt < 4; nt++) {
                mma_f16(acc[nt * 2],     a, &bbv[nt][0]);
                mma_f16(acc[nt * 2 + 1], a, &bbv[nt][2]);
            }
        }
    }
#undef ISSUE
#undef COMMIT

    // ALL groups must land before Af is reused as epilogue staging
    asm volatile("cp.async.wait_group 0;");
    __syncthreads();

    // Epilogue: +bias, row max, exp, fp16 store + g_S
    const int r0l = wm * 16 + grp;
    float v0[16], v1[16];
    float m0 = -1e30f, m1 = -1e30f;
#pragma unroll
    for (int nb = 0; nb < 8; nb++) {
#pragma unroll
        for (int h = 0; h < 2; h++) {
            int cc = nb * 8 + tig * 2 + h;
            float x0 = acc[nb][h]     + bs[cc];
            float x1 = acc[nb][2 + h] + bs[cc];
            v0[nb * 2 + h] = x0; v1[nb * 2 + h] = x1;
            m0 = fmaxf(m0, x0); m1 = fmaxf(m1, x1);
        }
    }
    m0 = fmaxf(m0, __shfl_xor_sync(0xffffffffu, m0, 1));
    m0 = fmaxf(m0, __shfl_xor_sync(0xffffffffu, m0, 2));
    m1 = fmaxf(m1, __shfl_xor_sync(0xffffffffu, m1, 1));
    m1 = fmaxf(m1, __shfl_xor_sync(0xffffffffu, m1, 2));

    __half* stage = (__half*)Af;   // 128 x 72 fp16 staging (safe after wait_group 0)
#pragma unroll
    for (int nb = 0; nb < 8; nb++) {
        *(uint32_t*)&stage[r0l * 72 + nb * 8 + tig * 2] =
            packh(__expf(v0[nb * 2] - m0), __expf(v0[nb * 2 + 1] - m0));
        *(uint32_t*)&stage[(r0l + 8) * 72 + nb * 8 + tig * 2] =
            packh(__expf(v1[nb * 2] - m1), __expf(v1[nb * 2 + 1] - m1));
    }
    if (tig == 0) { g_S[r0 + r0l] = m0; g_S[r0 + r0l + 8] = m1; }
    __syncwarp();
#pragma unroll
    for (int p = 0; p < 4; p++) {
        int q = lane + 32 * p;
        int rr = q >> 3, c16 = q & 7;
        uint4 d = *(uint4*)&stage[(wm * 16 + rr) * 72 + c16 * 8];
        *(uint4*)&g_E[(r0 + wm * 16 + rr) * 64 + c16 * 8] = d;
    }
}

// ---------------------------------------------------------------------------
// Subtree kernel + fused tail.  expTb loaded coalesced via cp.async from the
// precomputed global; Par double-buffered (prefetch hidden under MMA).
// ---------------------------------------------------------------------------
__global__ __launch_bounds__(256)
void subtree_kernel(float* __restrict__ out) {
    __shared__ __align__(16) char blob[45056];
    __shared__ float warpS[8];
    __shared__ float nodeLog[8];
    __shared__ float sGlob;
    __shared__ int   is_last;

    __half* Cur = (__half*)blob;              // 128*72*2 = 18432
    __half* Tb  = (__half*)(blob + 18432);    //  64*72*2 =  9216
    __half* Par = (__half*)(blob + 27648);    // 2 x 64*64*2 = 16384

    const int tid = threadIdx.x;
    const int wm = tid >> 5, lane = tid & 31;
    const int grp = lane >> 2, tig = lane & 3;
    const int b = blockIdx.x >> 3, j = blockIdx.x & 7;
    const size_t nb_base = (size_t)b * NNODES;

    const uint32_t cur_b = smem_u32(Cur), tb_b = smem_u32(Tb);
    const uint32_t par_b = smem_u32(Par);

    // initial loads: 128 leaf rows, expTb (coalesced), Par[0] for P=64
    const char* Lg = (const char*)(g_E + (nb_base + 1023 + 128 * j) * 64);
    for (int q = tid; q < 1024; q += 256) {
        int r = q >> 3, c = q & 7;
        cp16(cur_b + (uint32_t)(r * 72 + c * 8) * 2, Lg + q * 16);
    }
    const char* Tg = (const char*)g_expTb;
    for (int q = tid; q < 512; q += 256) {
        int r = q >> 3, c = q & 7;
        cp16(tb_b + (uint32_t)(r * 72 + c * 8) * 2, Tg + q * 16);
    }
    {
        const char* Pg = (const char*)(g_E + (nb_base + 511 + 64 * j) * 64);
        for (int q = tid; q < 512; q += 256)
            cp16(par_b + (uint32_t)(q * 16), Pg + q * 16);
    }
    asm volatile("cp.async.commit_group;");
    asm volatile("cp.async.wait_group 0;");
    __syncthreads();

    float lsum = 0.f;
    int parsel = 0;

#pragma unroll 1
    for (int P = 64; P >= 1; P >>= 1) {
        const int active = (wm * 16) < 2 * P;

        // prefetch NEXT level's parent rows into the other Par buffer
        if (P > 1) {
            const char* Pg = (const char*)(g_E + (nb_base + 4 * P - 1 + (P / 2) * j) * 64);
            const uint32_t pb = par_b + (uint32_t)(parsel ^ 1) * 8192;
            for (int q = tid; q < 4 * P; q += 256)
                cp16(pb + (uint32_t)(q * 16), Pg + q * 16);
            asm volatile("cp.async.commit_group;");
        }

        float acc[8][4];
#pragma unroll
        for (int nb = 0; nb < 8; nb++)
#pragma unroll
            for (int i = 0; i < 4; i++) acc[nb][i] = 0.f;

        if (active) {
#pragma unroll
            for (int kk = 0; kk < 4; kk++) {
                uint32_t a[4], bbv[4][4];
                ldsm_x4(a, cur_b + (uint32_t)((wm * 16 + (lane & 15)) * 72
                                              + kk * 16 + ((lane >> 4) << 3)) * 2);
#pragma unroll
                for (int nt = 0; nt < 4; nt++)
                    ldsm_x4_t(bbv[nt], tb_b + (uint32_t)((kk * 16 + (lane & 15)) * 72
                                                         + nt * 16 + ((lane >> 4) << 3)) * 2);
#pragma unroll
                for (int nt = 0; nt < 4; nt++) {
                    mma_f16(acc[nt * 2],     a, &bbv[nt][0]);
                    mma_f16(acc[nt * 2 + 1], a, &bbv[nt][2]);
                }
            }
        }
        __syncthreads();   // all Cur reads done -> epilogue may write Cur

        if (active) {
            const int p0 = wm * 8 + (grp >> 1);
            const int p1 = p0 + 4;
            const bool ok0 = p0 < P, ok1 = p1 < P;
            const __half* par = Par + parsel * 4096;

            float q0[16], q1[16];
            float C0 = 0.f, C1 = 0.f;
#pragma unroll
            for (int nb = 0; nb < 8; nb++) {
                float s00 = acc[nb][0], s01 = acc[nb][1];
                float s10 = acc[nb][2], s11 = acc[nb][3];
                float p00 = s00 * __shfl_xor_sync(0xffffffffu, s00, 4);
                float p01 = s01 * __shfl_xor_sync(0xffffffffu, s01, 4);
                float p10 = s10 * __shfl_xor_sync(0xffffffffu, s10, 4);
                float p11 = s11 * __shfl_xor_sync(0xffffffffu, s11, 4);
                uint32_t e0u = ok0 ? *(const uint32_t*)&par[p0 * 64 + nb * 8 + tig * 2] : 0u;
                uint32_t e1u = ok1 ? *(const uint32_t*)&par[p1 * 64 + nb * 8 + tig * 2] : 0u;
                float2 e0 = h2f2(e0u), e1 = h2f2(e1u);
                q0[nb * 2]     = e0.x * p00;
                q0[nb * 2 + 1] = e0.y * p01;
                q1[nb * 2]     = e1.x * p10;
                q1[nb * 2 + 1] = e1.y * p11;
                C0 = fmaxf(C0, fmaxf(q0[nb * 2], q0[nb * 2 + 1]));
                C1 = fmaxf(C1, fmaxf(q1[nb * 2], q1[nb * 2 + 1]));
            }
            C0 = fmaxf(C0, __shfl_xor_sync(0xffffffffu, C0, 1));
            C0 = fmaxf(C0, __shfl_xor_sync(0xffffffffu, C0, 2));
            C1 = fmaxf(C1, __shfl_xor_sync(0xffffffffu, C1, 1));
            C1 = fmaxf(C1, __shfl_xor_sync(0xffffffffu, C1, 2));
            float i0 = __fdividef(1.0f, C0), i1 = __fdividef(1.0f, C1);

            if (!(grp & 1)) {
                if (ok0) {
#pragma unroll
                    for (int nb = 0; nb < 8; nb++)
                        *(uint32_t*)&Cur[p0 * 72 + nb * 8 + tig * 2] =
                            packh(q0[nb * 2] * i0, q0[nb * 2 + 1] * i0);
                }
                if (ok1) {
#pragma unroll
                    for (int nb = 0; nb < 8; nb++)
                        *(uint32_t*)&Cur[p1 * 72 + nb * 8 + tig * 2] =
                            packh(q1[nb * 2] * i1, q1[nb * 2 + 1] * i1);
                }
                if (tig == 0) {
                    if (ok0) lsum += __logf(C0);
                    if (ok1) lsum += __logf(C1);
                }
            }
        }
        asm volatile("cp.async.wait_group 0;");  // next Par arrived (overlapped)
        __syncthreads();
        parsel ^= 1;
    }

    if (tid < 8)
        *(uint4*)&g_E[(nb_base + 7 + j) * 64 + tid * 8] = *(uint4*)&Cur[tid * 8];

#pragma unroll
    for (int o = 16; o > 0; o >>= 1) lsum += __shfl_xor_sync(0xffffffffu, lsum, o);
    if (lane == 0) warpS[wm] = lsum;
    __syncthreads();
    if (tid == 0) {
        float t = 0.f;
        for (int i = 0; i < 8; i++) t += warpS[i];
        g_S[nb_base + 7 + j] += t;
    }

    // -------- completion protocol: last CTA of this batch runs the tail -----
    __threadfence();
    __syncthreads();
    if (tid == 0) {
        int old = atomicAdd(&g_cnt[b], 1);
        is_last = (old == 7);
    }
    __syncthreads();
    if (!is_last) return;
    __threadfence();

    // -------- tail phase (overlaid smem) ------------------------------------
    float*  Eb  = (float*)blob;            // 15*64*4 = 3840
    float2* Ept = (float2*)(blob + 4096);  // 2048*8 = 16384

    for (int i = tid; i < NLAB * 32; i += 256) Ept[i] = g_expT[i];
    const uint32_t* srcE = (const uint32_t*)(g_E + nb_base * 64);
    for (int i = tid; i < 480; i += 256) {
        float2 f = h2f2(srcE[i]);
        Eb[2 * i]     = f.x;
        Eb[2 * i + 1] = f.y;
    }
    float s = 0.f;
    const float* Sb = g_S + nb_base;
    for (int i = tid; i < NNODES; i += 256) s += Sb[i];
#pragma unroll
    for (int o = 16; o > 0; o >>= 1) s += __shfl_xor_sync(0xffffffffu, s, o);
    if (lane == 0) warpS[wm] = s;
    __syncthreads();
    if (tid == 0) {
        float t = 0.f;
        for (int i = 0; i < 8; i++) t += warpS[i];
        sGlob = t;
    }
    __syncthreads();

    // phase 1: nodes 3..6 on warps 0..3
    if (wm < 4) {
        int p = 3 + wm, cL = 2 * p + 1, cR = 2 * p + 2;
        float aL0 = 0.f, aL1 = 0.f, aR0 = 0.f, aR1 = 0.f;
#pragma unroll
        for (int k = 0; k < NLAB; k++) {
            float2 tt = Ept[k * 32 + lane];
            float uL = Eb[cL * 64 + k], uR = Eb[cR * 64 + k];
            aL0 = fmaf(tt.x, uL, aL0); aL1 = fmaf(tt.y, uL, aL1);
            aR0 = fmaf(tt.x, uR, aR0); aR1 = fmaf(tt.y, uR, aR1);
        }
        float q0 = Eb[p * 64 + lane]      * aL0 * aR0;
        float q1 = Eb[p * 64 + lane + 32] * aL1 * aR1;
        float C = fmaxf(q0, q1);
#pragma unroll
        for (int o = 16; o > 0; o >>= 1) C = fmaxf(C, __shfl_xor_sync(0xffffffffu, C, o));
        float inv = __fdividef(1.0f, C);
        Eb[p * 64 + lane]      = q0 * inv;
        Eb[p * 64 + lane + 32] = q1 * inv;
        if (lane == 0) nodeLog[wm] = __logf(C);
    }
    __syncthreads();

    // phase 2: nodes 1,2 on warps 0,1
    if (wm < 2) {
        int p = 1 + wm, cL = 2 * p + 1, cR = 2 * p + 2;
        float aL0 = 0.f, aL1 = 0.f, aR0 = 0.f, aR1 = 0.f;
#pragma unroll
        for (int k = 0; k < NLAB; k++) {
            float2 tt = Ept[k * 32 + lane];
            float uL = Eb[cL * 64 + k], uR = Eb[cR * 64 + k];
            aL0 = fmaf(tt.x, uL, aL0); aL1 = fmaf(tt.y, uL, aL1);
            aR0 = fmaf(tt.x, uR, aR0); aR1 = fmaf(tt.y, uR, aR1);
        }
        float q0 = Eb[p * 64 + lane]      * aL0 * aR0;
        float q1 = Eb[p * 64 + lane + 32] * aL1 * aR1;
        float C = fmaxf(q0, q1);
#pragma unroll
        for (int o = 16; o > 0; o >>= 1) C = fmaxf(C, __shfl_xor_sync(0xffffffffu, C, o));
        float inv = __fdividef(1.0f, C);
        Eb[p * 64 + lane]      = q0 * inv;
        Eb[p * 64 + lane + 32] = q1 * inv;
        if (lane == 0) nodeLog[4 + wm] = __logf(C);
    }
    __syncthreads();

    // phase 3: root on warp 0
    if (wm == 0) {
        float aL0 = 0.f, aL1 = 0.f, aR0 = 0.f, aR1 = 0.f;
#pragma unroll
        for (int k = 0; k < NLAB; k++) {
            float2 tt = Ept[k * 32 + lane];
            float uL = Eb[64 + k], uR = Eb[128 + k];
            aL0 = fmaf(tt.x, uL, aL0); aL1 = fmaf(tt.y, uL, aL1);
            aR0 = fmaf(tt.x, uR, aR0); aR1 = fmaf(tt.y, uR, aR1);
        }
        float q0 = Eb[lane]      * aL0 * aR0;
        float q1 = Eb[lane + 32] * aL1 * aR1;
        float S = sGlob + nodeLog[0] + nodeLog[1] + nodeLog[2]
                        + nodeLog[3] + nodeLog[4] + nodeLog[5];
        out[b * NLAB + lane]      = S + __logf(q0);
        out[b * NLAB + lane + 32] = S + __logf(q1);
    }
}

// ---------------------------------------------------------------------------
// Launcher
// ---------------------------------------------------------------------------
extern "C" void kernel_launch(void* const* d_in, const int* in_sizes, int n_in,
                              void* d_out, int out_size) {
    const float* hidden = (const float*)d_in[0];
    const float* W      = (const float*)d_in[1];
    const float* bias   = (const float*)d_in[2];
    const float* trans  = (const float*)d_in[3];
    float* out = (float*)d_out;

    init_all<<<32, 256>>>(trans, W);
    gemm_kernel<<<NNODES, 256>>>(hidden, bias);
    subtree_kernel<<<BATCH * 8, 256>>>(out);
}